// round 3
// baseline (speedup 1.0000x reference)
#include <cuda_runtime.h>
#include <math.h>

#define BATCH 256
#define TLEN 512
#define CO 320
#define NSUBJ 4
#define BN_EPS 1e-5f

// ---------------------------------------------------------------------------
// Scratch (device globals; no allocation allowed)
// ---------------------------------------------------------------------------
__device__ float g_y[(size_t)BATCH * CO * TLEN];   // conv output (pre-BN)
__device__ float g_a[(size_t)BATCH * CO * TLEN];   // post BN+GELU activation
__device__ float g_bsum[BATCH * CO];               // per-(b,c) sum over T
__device__ float g_bsum2[BATCH * CO];              // per-(b,c) sum of squares
__device__ float g_scale[NSUBJ * CO];
__device__ float g_shift[NSUBJ * CO];

// ---------------------------------------------------------------------------
// Conv1d K=3 SAME, implicit GEMM.
// Tile: 64 cout x 64 t per block, 256 threads, 4co x 4t per thread.
// Cin chunked by 8 through shared memory. Optional residual add.
// ---------------------------------------------------------------------------
__global__ __launch_bounds__(256) void conv3_kernel(
    const float* __restrict__ x,     // [B, Cin, T]
    const float* __restrict__ w,     // [CO, Cin, 3]
    const float* __restrict__ bias,  // [CO]
    const float* __restrict__ res,   // [B, CO, T] or nullptr
    float* __restrict__ y,           // [B, CO, T]
    int Cin)
{
    const int b   = blockIdx.z;
    const int co0 = blockIdx.y * 64;
    const int t0  = blockIdx.x * 64;
    const int tid = threadIdx.x;
    const int tx  = tid & 15;   // t sub-tile: 4 outputs at t0 + tx*4
    const int ty  = tid >> 4;   // co sub-tile: 4 outputs at co0 + ty*4

    __shared__ float sx[8][68];      // [ci][t + halo], padded row for .128 alignment
    __shared__ float sw[64][24];     // [co][ci*3 + k]

    float acc[4][4];
#pragma unroll
    for (int i = 0; i < 4; i++)
#pragma unroll
        for (int j = 0; j < 4; j++) acc[i][j] = 0.f;

    const float* xb = x + (size_t)b * Cin * TLEN;

    for (int c0 = 0; c0 < Cin; c0 += 8) {
        const int ck = min(8, Cin - c0);

        // stage x tile (8 x 66 incl. halo; zero-pad channels & borders)
        for (int i = tid; i < 8 * 66; i += 256) {
            int ci = i / 66;
            int tt = i - ci * 66;
            int gt = t0 + tt - 1;
            float v = 0.f;
            if (ci < ck && (unsigned)gt < (unsigned)TLEN)
                v = xb[(size_t)(c0 + ci) * TLEN + gt];
            sx[ci][tt] = v;
        }
        // stage w tile (64 co x 8 ci x 3 taps; zero-pad tail channels)
        for (int i = tid; i < 64 * 24; i += 256) {
            int co = i / 24;
            int r  = i - co * 24;
            int ci = r / 3;
            int k  = r - ci * 3;
            float v = 0.f;
            if (ci < ck)
                v = w[((size_t)(co0 + co) * Cin + (c0 + ci)) * 3 + k];
            sw[co][r] = v;
        }
        __syncthreads();

#pragma unroll
        for (int ci = 0; ci < 8; ci++) {
            float xr[6];
#pragma unroll
            for (int j = 0; j < 6; j++) xr[j] = sx[ci][tx * 4 + j];
#pragma unroll
            for (int cc = 0; cc < 4; cc++) {
                const float w0 = sw[ty * 4 + cc][ci * 3 + 0];
                const float w1 = sw[ty * 4 + cc][ci * 3 + 1];
                const float w2 = sw[ty * 4 + cc][ci * 3 + 2];
#pragma unroll
                for (int tt = 0; tt < 4; tt++)
                    acc[cc][tt] = fmaf(w0, xr[tt],
                                  fmaf(w1, xr[tt + 1],
                                  fmaf(w2, xr[tt + 2], acc[cc][tt])));
            }
        }
        __syncthreads();
    }

    // epilogue: bias (+ residual)
#pragma unroll
    for (int cc = 0; cc < 4; cc++) {
        const int co = co0 + ty * 4 + cc;
        const float bv = __ldg(&bias[co]);
        const size_t base = ((size_t)b * CO + co) * TLEN + t0 + tx * 4;
        if (res) {
#pragma unroll
            for (int tt = 0; tt < 4; tt++)
                y[base + tt] = acc[cc][tt] + bv + __ldg(&res[base + tt]);
        } else {
#pragma unroll
            for (int tt = 0; tt < 4; tt++)
                y[base + tt] = acc[cc][tt] + bv;
        }
    }
}

// ---------------------------------------------------------------------------
// Stage 1 of BN stats: one warp per (b, c) row -> partial sum / sumsq.
// ---------------------------------------------------------------------------
__global__ __launch_bounds__(256) void stats_kernel(
    const float* __restrict__ y, float* __restrict__ bs, float* __restrict__ bs2)
{
    const int warp = (int)((blockIdx.x * (size_t)blockDim.x + threadIdx.x) >> 5);
    const int lane = threadIdx.x & 31;
    if (warp >= BATCH * CO) return;
    const float4* p = (const float4*)(y + (size_t)warp * TLEN);
    float s = 0.f, s2 = 0.f;
#pragma unroll
    for (int i = lane; i < TLEN / 4; i += 32) {
        float4 v = p[i];
        s  += v.x + v.y + v.z + v.w;
        s2 += v.x * v.x + v.y * v.y + v.z * v.z + v.w * v.w;
    }
#pragma unroll
    for (int o = 16; o; o >>= 1) {
        s  += __shfl_xor_sync(0xFFFFFFFFu, s,  o);
        s2 += __shfl_xor_sync(0xFFFFFFFFu, s2, o);
    }
    if (lane == 0) { bs[warp] = s; bs2[warp] = s2; }
}

// ---------------------------------------------------------------------------
// Stage 2: reduce per-(b,c) partials into per-(subject,c) scale/shift.
// ---------------------------------------------------------------------------
__global__ __launch_bounds__(256) void scaleshift_kernel(
    const float* __restrict__ bs, const float* __restrict__ bs2,
    const int* __restrict__ subj,
    const float* __restrict__ gamma, const float* __restrict__ beta,
    float* __restrict__ scale_out, float* __restrict__ shift_out)
{
    const int i = blockIdx.x * blockDim.x + threadIdx.x;   // s*CO + c
    if (i >= NSUBJ * CO) return;
    const int s = i / CO;
    const int c = i - s * CO;
    float sum = 0.f, sum2 = 0.f, cntb = 0.f;
    for (int b = 0; b < BATCH; b++) {
        if (subj[b] == s) {
            sum  += bs[b * CO + c];
            sum2 += bs2[b * CO + c];
            cntb += 1.f;
        }
    }
    const float cnt  = fmaxf(cntb * (float)TLEN, 1.f);
    const float mean = sum / cnt;
    const float var  = sum2 / cnt - mean * mean;
    const float sc   = gamma[i] * rsqrtf(var + BN_EPS);
    scale_out[i] = sc;
    shift_out[i] = beta[i] - mean * sc;
}

// ---------------------------------------------------------------------------
// Stage 3: fused BN apply + exact-erf GELU, float4 vectorized.
// ---------------------------------------------------------------------------
__device__ __forceinline__ float gelu_exact(float u) {
    return 0.5f * u * (1.f + erff(u * 0.70710678118654752440f));
}

__global__ __launch_bounds__(256) void bn_gelu_kernel(
    const float* __restrict__ y, const int* __restrict__ subj,
    const float* __restrict__ scale, const float* __restrict__ shift,
    float* __restrict__ out)
{
    const size_t n4  = (size_t)BATCH * CO * TLEN / 4;
    const size_t idx = (size_t)blockIdx.x * blockDim.x + threadIdx.x;
    if (idx >= n4) return;
    const size_t e  = idx * 4;
    const int bc = (int)(e / TLEN);          // b*CO + c  (T divisible by 4)
    const int b  = bc / CO;
    const int c  = bc - b * CO;
    const int s  = __ldg(&subj[b]);
    const float sc = __ldg(&scale[s * CO + c]);
    const float sh = __ldg(&shift[s * CO + c]);
    float4 v = ((const float4*)y)[idx];
    v.x = gelu_exact(fmaf(v.x, sc, sh));
    v.y = gelu_exact(fmaf(v.y, sc, sh));
    v.z = gelu_exact(fmaf(v.z, sc, sh));
    v.w = gelu_exact(fmaf(v.w, sc, sh));
    ((float4*)out)[idx] = v;
}

// ---------------------------------------------------------------------------
// Host orchestration
// ---------------------------------------------------------------------------
static void run_bn_gelu(const float* y, const int* subj,
                        const float* gamma, const float* beta,
                        float* bsum, float* bsum2, float* scale, float* shift,
                        float* out)
{
    const int nrows = BATCH * CO;
    // stage 1: one warp per row
    {
        const size_t threads = (size_t)nrows * 32;
        stats_kernel<<<(unsigned)((threads + 255) / 256), 256>>>(y, bsum, bsum2);
    }
    // stage 2
    scaleshift_kernel<<<(NSUBJ * CO + 255) / 256, 256>>>(bsum, bsum2, subj,
                                                         gamma, beta, scale, shift);
    // stage 3
    {
        const size_t n4 = (size_t)BATCH * CO * TLEN / 4;
        bn_gelu_kernel<<<(unsigned)((n4 + 255) / 256), 256>>>(y, subj, scale, shift, out);
    }
}

extern "C" void kernel_launch(void* const* d_in, const int* in_sizes, int n_in,
                              void* d_out, int out_size)
{
    const float* X    = (const float*)d_in[0];   // [256, 271, 512]
    const int*   subj = (const int*)  d_in[1];   // [256]
    const float* w0   = (const float*)d_in[2];
    const float* b0   = (const float*)d_in[3];
    const float* w1   = (const float*)d_in[4];
    const float* b1   = (const float*)d_in[5];
    const float* w2   = (const float*)d_in[6];
    const float* b2   = (const float*)d_in[7];
    const float* g0   = (const float*)d_in[8];
    const float* be0  = (const float*)d_in[9];
    const float* g1   = (const float*)d_in[10];
    const float* be1  = (const float*)d_in[11];
    const float* g2   = (const float*)d_in[12];
    const float* be2  = (const float*)d_in[13];
    float* out = (float*)d_out;

    const int Cin0 = in_sizes[0] / (BATCH * TLEN);   // 271

    float *py, *pa, *pbs, *pbs2, *psc, *psh;
    cudaGetSymbolAddress((void**)&py,   g_y);
    cudaGetSymbolAddress((void**)&pa,   g_a);
    cudaGetSymbolAddress((void**)&pbs,  g_bsum);
    cudaGetSymbolAddress((void**)&pbs2, g_bsum2);
    cudaGetSymbolAddress((void**)&psc,  g_scale);
    cudaGetSymbolAddress((void**)&psh,  g_shift);

    dim3 cgrid(TLEN / 64, CO / 64, BATCH);   // (8, 5, 256)

    // layer 0: conv(X) -> y ; BN+GELU -> a
    conv3_kernel<<<cgrid, 256>>>(X, w0, b0, nullptr, py, Cin0);
    run_bn_gelu(py, subj, g0, be0, pbs, pbs2, psc, psh, pa);

    // layer 1: conv(a) + a -> y ; BN+GELU -> a
    conv3_kernel<<<cgrid, 256>>>(pa, w1, b1, pa, py, CO);
    run_bn_gelu(py, subj, g1, be1, pbs, pbs2, psc, psh, pa);

    // layer 2: conv(a) + a -> y ; BN+GELU -> out
    conv3_kernel<<<cgrid, 256>>>(pa, w2, b2, pa, py, CO);
    run_bn_gelu(py, subj, g2, be2, pbs, pbs2, psc, psh, out);
}

// round 4
// speedup vs baseline: 1.0012x; 1.0012x over previous
#include <cuda_runtime.h>
#include <math.h>

#define BATCH 256
#define TLEN 512
#define CO 320
#define NSUBJ 4
#define BN_EPS 1e-5f

// ---------------------------------------------------------------------------
// Scratch (device globals; no allocation allowed)
// ---------------------------------------------------------------------------
__device__ float g_y[(size_t)BATCH * CO * TLEN];   // conv output (pre-BN)
__device__ float g_a[(size_t)BATCH * CO * TLEN];   // post BN+GELU activation
__device__ float g_bsum[BATCH * CO];               // per-(b,c) sum over T
__device__ float g_bsum2[BATCH * CO];              // per-(b,c) sum of squares
__device__ float g_scale[NSUBJ * CO];
__device__ float g_shift[NSUBJ * CO];

// ---------------------------------------------------------------------------
// Conv1d K=3 SAME, implicit GEMM.
// Tile: 64 cout x 64 t per block, 256 threads, 4co x 4t per thread.
// Cin chunked by 8 through shared memory. Optional residual add.
// ---------------------------------------------------------------------------
__global__ __launch_bounds__(256) void conv3_kernel(
    const float* __restrict__ x,     // [B, Cin, T]
    const float* __restrict__ w,     // [CO, Cin, 3]
    const float* __restrict__ bias,  // [CO]
    const float* __restrict__ res,   // [B, CO, T] or nullptr
    float* __restrict__ y,           // [B, CO, T]
    int Cin)
{
    const int b   = blockIdx.z;
    const int co0 = blockIdx.y * 64;
    const int t0  = blockIdx.x * 64;
    const int tid = threadIdx.x;
    const int tx  = tid & 15;   // t sub-tile: 4 outputs at t0 + tx*4
    const int ty  = tid >> 4;   // co sub-tile: 4 outputs at co0 + ty*4

    __shared__ float sx[8][68];      // [ci][t + halo], padded row for .128 alignment
    __shared__ float sw[64][24];     // [co][ci*3 + k]

    float acc[4][4];
#pragma unroll
    for (int i = 0; i < 4; i++)
#pragma unroll
        for (int j = 0; j < 4; j++) acc[i][j] = 0.f;

    const float* xb = x + (size_t)b * Cin * TLEN;

    for (int c0 = 0; c0 < Cin; c0 += 8) {
        const int ck = min(8, Cin - c0);

        // stage x tile (8 x 66 incl. halo; zero-pad channels & borders)
        for (int i = tid; i < 8 * 66; i += 256) {
            int ci = i / 66;
            int tt = i - ci * 66;
            int gt = t0 + tt - 1;
            float v = 0.f;
            if (ci < ck && (unsigned)gt < (unsigned)TLEN)
                v = xb[(size_t)(c0 + ci) * TLEN + gt];
            sx[ci][tt] = v;
        }
        // stage w tile (64 co x 8 ci x 3 taps; zero-pad tail channels)
        for (int i = tid; i < 64 * 24; i += 256) {
            int co = i / 24;
            int r  = i - co * 24;
            int ci = r / 3;
            int k  = r - ci * 3;
            float v = 0.f;
            if (ci < ck)
                v = w[((size_t)(co0 + co) * Cin + (c0 + ci)) * 3 + k];
            sw[co][r] = v;
        }
        __syncthreads();

#pragma unroll
        for (int ci = 0; ci < 8; ci++) {
            float xr[6];
#pragma unroll
            for (int j = 0; j < 6; j++) xr[j] = sx[ci][tx * 4 + j];
#pragma unroll
            for (int cc = 0; cc < 4; cc++) {
                const float w0 = sw[ty * 4 + cc][ci * 3 + 0];
                const float w1 = sw[ty * 4 + cc][ci * 3 + 1];
                const float w2 = sw[ty * 4 + cc][ci * 3 + 2];
#pragma unroll
                for (int tt = 0; tt < 4; tt++)
                    acc[cc][tt] = fmaf(w0, xr[tt],
                                  fmaf(w1, xr[tt + 1],
                                  fmaf(w2, xr[tt + 2], acc[cc][tt])));
            }
        }
        __syncthreads();
    }

    // epilogue: bias (+ residual)
#pragma unroll
    for (int cc = 0; cc < 4; cc++) {
        const int co = co0 + ty * 4 + cc;
        const float bv = __ldg(&bias[co]);
        const size_t base = ((size_t)b * CO + co) * TLEN + t0 + tx * 4;
        if (res) {
#pragma unroll
            for (int tt = 0; tt < 4; tt++)
                y[base + tt] = acc[cc][tt] + bv + __ldg(&res[base + tt]);
        } else {
#pragma unroll
            for (int tt = 0; tt < 4; tt++)
                y[base + tt] = acc[cc][tt] + bv;
        }
    }
}

// ---------------------------------------------------------------------------
// Stage 1 of BN stats: one warp per (b, c) row -> partial sum / sumsq.
// ---------------------------------------------------------------------------
__global__ __launch_bounds__(256) void stats_kernel(
    const float* __restrict__ y, float* __restrict__ bs, float* __restrict__ bs2)
{
    const int warp = (int)((blockIdx.x * (size_t)blockDim.x + threadIdx.x) >> 5);
    const int lane = threadIdx.x & 31;
    if (warp >= BATCH * CO) return;
    const float4* p = (const float4*)(y + (size_t)warp * TLEN);
    float s = 0.f, s2 = 0.f;
#pragma unroll
    for (int i = lane; i < TLEN / 4; i += 32) {
        float4 v = p[i];
        s  += v.x + v.y + v.z + v.w;
        s2 += v.x * v.x + v.y * v.y + v.z * v.z + v.w * v.w;
    }
#pragma unroll
    for (int o = 16; o; o >>= 1) {
        s  += __shfl_xor_sync(0xFFFFFFFFu, s,  o);
        s2 += __shfl_xor_sync(0xFFFFFFFFu, s2, o);
    }
    if (lane == 0) { bs[warp] = s; bs2[warp] = s2; }
}

// ---------------------------------------------------------------------------
// Stage 2: reduce per-(b,c) partials into per-(subject,c) scale/shift.
// ---------------------------------------------------------------------------
__global__ __launch_bounds__(256) void scaleshift_kernel(
    const float* __restrict__ bs, const float* __restrict__ bs2,
    const int* __restrict__ subj,
    const float* __restrict__ gamma, const float* __restrict__ beta,
    float* __restrict__ scale_out, float* __restrict__ shift_out)
{
    const int i = blockIdx.x * blockDim.x + threadIdx.x;   // s*CO + c
    if (i >= NSUBJ * CO) return;
    const int s = i / CO;
    const int c = i - s * CO;
    float sum = 0.f, sum2 = 0.f, cntb = 0.f;
    for (int b = 0; b < BATCH; b++) {
        if (subj[b] == s) {
            sum  += bs[b * CO + c];
            sum2 += bs2[b * CO + c];
            cntb += 1.f;
        }
    }
    const float cnt  = fmaxf(cntb * (float)TLEN, 1.f);
    const float mean = sum / cnt;
    const float var  = sum2 / cnt - mean * mean;
    const float sc   = gamma[i] * rsqrtf(var + BN_EPS);
    scale_out[i] = sc;
    shift_out[i] = beta[i] - mean * sc;
}

// ---------------------------------------------------------------------------
// Stage 3: fused BN apply + exact-erf GELU, float4 vectorized.
// ---------------------------------------------------------------------------
__device__ __forceinline__ float gelu_exact(float u) {
    return 0.5f * u * (1.f + erff(u * 0.70710678118654752440f));
}

__global__ __launch_bounds__(256) void bn_gelu_kernel(
    const float* __restrict__ y, const int* __restrict__ subj,
    const float* __restrict__ scale, const float* __restrict__ shift,
    float* __restrict__ out)
{
    const size_t n4  = (size_t)BATCH * CO * TLEN / 4;
    const size_t idx = (size_t)blockIdx.x * blockDim.x + threadIdx.x;
    if (idx >= n4) return;
    const size_t e  = idx * 4;
    const int bc = (int)(e / TLEN);          // b*CO + c  (T divisible by 4)
    const int b  = bc / CO;
    const int c  = bc - b * CO;
    const int s  = __ldg(&subj[b]);
    const float sc = __ldg(&scale[s * CO + c]);
    const float sh = __ldg(&shift[s * CO + c]);
    float4 v = ((const float4*)y)[idx];
    v.x = gelu_exact(fmaf(v.x, sc, sh));
    v.y = gelu_exact(fmaf(v.y, sc, sh));
    v.z = gelu_exact(fmaf(v.z, sc, sh));
    v.w = gelu_exact(fmaf(v.w, sc, sh));
    ((float4*)out)[idx] = v;
}

// ---------------------------------------------------------------------------
// Host orchestration
// ---------------------------------------------------------------------------
static void run_bn_gelu(const float* y, const int* subj,
                        const float* gamma, const float* beta,
                        float* bsum, float* bsum2, float* scale, float* shift,
                        float* out)
{
    const int nrows = BATCH * CO;
    // stage 1: one warp per row
    {
        const size_t threads = (size_t)nrows * 32;
        stats_kernel<<<(unsigned)((threads + 255) / 256), 256>>>(y, bsum, bsum2);
    }
    // stage 2
    scaleshift_kernel<<<(NSUBJ * CO + 255) / 256, 256>>>(bsum, bsum2, subj,
                                                         gamma, beta, scale, shift);
    // stage 3
    {
        const size_t n4 = (size_t)BATCH * CO * TLEN / 4;
        bn_gelu_kernel<<<(unsigned)((n4 + 255) / 256), 256>>>(y, subj, scale, shift, out);
    }
}

extern "C" void kernel_launch(void* const* d_in, const int* in_sizes, int n_in,
                              void* d_out, int out_size)
{
    const float* X    = (const float*)d_in[0];   // [256, 271, 512]
    const int*   subj = (const int*)  d_in[1];   // [256]
    const float* w0   = (const float*)d_in[2];
    const float* b0   = (const float*)d_in[3];
    const float* w1   = (const float*)d_in[4];
    const float* b1   = (const float*)d_in[5];
    const float* w2   = (const float*)d_in[6];
    const float* b2   = (const float*)d_in[7];
    const float* g0   = (const float*)d_in[8];
    const float* be0  = (const float*)d_in[9];
    const float* g1   = (const float*)d_in[10];
    const float* be1  = (const float*)d_in[11];
    const float* g2   = (const float*)d_in[12];
    const float* be2  = (const float*)d_in[13];
    float* out = (float*)d_out;

    const int Cin0 = in_sizes[0] / (BATCH * TLEN);   // 271

    float *py, *pa, *pbs, *pbs2, *psc, *psh;
    cudaGetSymbolAddress((void**)&py,   g_y);
    cudaGetSymbolAddress((void**)&pa,   g_a);
    cudaGetSymbolAddress((void**)&pbs,  g_bsum);
    cudaGetSymbolAddress((void**)&pbs2, g_bsum2);
    cudaGetSymbolAddress((void**)&psc,  g_scale);
    cudaGetSymbolAddress((void**)&psh,  g_shift);

    dim3 cgrid(TLEN / 64, CO / 64, BATCH);   // (8, 5, 256)

    // layer 0: conv(X) -> y ; BN+GELU -> a
    conv3_kernel<<<cgrid, 256>>>(X, w0, b0, nullptr, py, Cin0);
    run_bn_gelu(py, subj, g0, be0, pbs, pbs2, psc, psh, pa);

    // layer 1: conv(a) + a -> y ; BN+GELU -> a
    conv3_kernel<<<cgrid, 256>>>(pa, w1, b1, pa, py, CO);
    run_bn_gelu(py, subj, g1, be1, pbs, pbs2, psc, psh, pa);

    // layer 2: conv(a) + a -> y ; BN+GELU -> out
    conv3_kernel<<<cgrid, 256>>>(pa, w2, b2, pa, py, CO);
    run_bn_gelu(py, subj, g2, be2, pbs, pbs2, psc, psh, out);
}

// round 5
// speedup vs baseline: 1.2270x; 1.2255x over previous
#include <cuda_runtime.h>
#include <math.h>

typedef unsigned long long ull;

#define BATCH 256
#define TLEN 512
#define CO 320
#define NSUBJ 4
#define BN_EPS 1e-5f
#define WT_STRIDE (320 * 3 * 320)

// ---------------------------------------------------------------------------
// Scratch (device globals; no allocation allowed)
// ---------------------------------------------------------------------------
__device__ float g_y[(size_t)BATCH * CO * TLEN];   // conv output (pre-BN)
__device__ float g_a[(size_t)BATCH * CO * TLEN];   // post BN+GELU activation
__device__ float g_wt[3][WT_STRIDE];               // transposed zero-padded weights
__device__ float g_bsum[BATCH * CO];
__device__ float g_bsum2[BATCH * CO];
__device__ float g_scale[NSUBJ * CO];
__device__ float g_shift[NSUBJ * CO];

// ---------------------------------------------------------------------------
// Packed fp32x2 FMA (Blackwell; ptxas never emits this from C++)
// ---------------------------------------------------------------------------
__device__ __forceinline__ ull ffma2(ull a, ull b, ull c) {
    ull d;
    asm("fma.rn.f32x2 %0, %1, %2, %3;" : "=l"(d) : "l"(a), "l"(b), "l"(c));
    return d;
}
__device__ __forceinline__ float2 ull2f2(ull v) {
    float2 r;
    r.x = __uint_as_float((unsigned)v);
    r.y = __uint_as_float((unsigned)(v >> 32));
    return r;
}

// ---------------------------------------------------------------------------
// Weight transpose: w[CO][Cin][3] -> wt[CinPad*3][CO], zero-padded rows.
// ---------------------------------------------------------------------------
__global__ __launch_bounds__(256) void wtrans_kernel(
    const float* __restrict__ w, float* __restrict__ wt, int Cin, int CinPad)
{
    const int i = blockIdx.x * blockDim.x + threadIdx.x;
    const int total = CinPad * 3 * CO;
    if (i >= total) return;
    const int co  = i % CO;
    const int row = i / CO;        // ci*3 + k
    const int ci  = row / 3;
    const int k   = row - ci * 3;
    wt[i] = (ci < Cin) ? w[((size_t)co * Cin + ci) * 3 + k] : 0.f;
}

// ---------------------------------------------------------------------------
// Conv1d K=3 SAME using packed fp32x2 FMAs.
// Block tile: 64 co x 128 t, 256 threads; per thread 4 co x 8 t (4 t-pairs).
// x staged as even-start and odd-start float2 pairs (skewed, conflict-free);
// weights staged duplicated (w,w) for broadcast pair-loads.
// ---------------------------------------------------------------------------
__global__ __launch_bounds__(256) void conv3_f32x2_kernel(
    const float* __restrict__ x,     // [B, Cin, T]
    const float* __restrict__ wt,    // [CinPad*3, CO] transposed, zero-padded
    const float* __restrict__ bias,  // [CO]
    const float* __restrict__ res,   // [B, CO, T] or nullptr
    float* __restrict__ y,           // [B, CO, T]
    int Cin)
{
    const int b   = blockIdx.z;
    const int co0 = blockIdx.y * 64;
    const int t0  = blockIdx.x * 128;
    const int tid = threadIdx.x;
    const int tx  = tid & 15;        // t: 8 outputs at t0 + tx*8
    const int ty  = tid >> 4;        // co: 4 outputs at co0 + ty*4
    const int tx4 = tx * 4;          // base t-pair index
    const int col = ty * 4;          // base co within tile

    __shared__ float2 sxe[8][68];    // even pairs (x[2m], x[2m+1]),  m<64, skewed
    __shared__ float2 sxo[8][72];    // odd  pairs (x[2m-1], x[2m]),  m<=64, skewed
    __shared__ float2 swd[8 * 3 * 64];  // dup weights [(ci*3+k)*64 + co] = (w,w)

    // Precompute skewed pair indices (invariant across ci / chunks)
    int exi[4], oxi[5];
#pragma unroll
    for (int p = 0; p < 4; p++) { int u = tx4 + p; exi[p] = u + (u >> 4); }
#pragma unroll
    for (int p = 0; p < 5; p++) { int u = tx4 + p; oxi[p] = u + (u >> 4); }

    ull acc[4][4];
#pragma unroll
    for (int i = 0; i < 4; i++)
#pragma unroll
        for (int j = 0; j < 4; j++) acc[i][j] = 0ull;

    const float* xb = x + (size_t)b * Cin * TLEN;

    for (int c0 = 0; c0 < Cin; c0 += 8) {
        const int ck = (Cin - c0 >= 8) ? 8 : (Cin - c0);

        // ---- stage x: even-start pairs (aligned float2 gmem loads) ----
        for (int i = tid; i < 512; i += 256) {
            const int ci = i >> 6, m = i & 63;
            float2 v = make_float2(0.f, 0.f);
            if (ci < ck)
                v = *(const float2*)(xb + (size_t)(c0 + ci) * TLEN + t0 + 2 * m);
            sxe[ci][m + (m >> 4)] = v;
        }
        // ---- stage x: odd-start pairs (2 scalar loads, boundary-predicated) ----
        for (int i = tid; i < 520; i += 256) {
            int ci, m;
            if (i < 512) { ci = i >> 6; m = i & 63; } else { ci = i - 512; m = 64; }
            float2 v = make_float2(0.f, 0.f);
            if (ci < ck) {
                const float* row = xb + (size_t)(c0 + ci) * TLEN;
                const int gt = t0 + 2 * m - 1;
                v.x = (gt >= 0) ? row[gt] : 0.f;
                v.y = (gt + 1 < TLEN) ? row[gt + 1] : 0.f;
            }
            sxo[ci][m + (m >> 4)] = v;
        }
        // ---- stage weights: duplicated pairs, branch-free (wt zero-padded) ----
        {
            const float* wrow = wt + (size_t)(c0 * 3) * CO + co0;
            for (int i = tid; i < 1536; i += 256) {
                const int r = i >> 6, co = i & 63;
                const float wv = wrow[(size_t)r * CO + co];
                swd[r * 64 + co] = make_float2(wv, wv);
            }
        }
        __syncthreads();

#pragma unroll
        for (int ci = 0; ci < 8; ci++) {
            const ull* rowe = (const ull*)&sxe[ci][0];
            const ull* rowo = (const ull*)&sxo[ci][0];
            ull xe[4], xo[5];
#pragma unroll
            for (int p = 0; p < 4; p++) xe[p] = rowe[exi[p]];
#pragma unroll
            for (int p = 0; p < 5; p++) xo[p] = rowo[oxi[p]];

            const ull* wrow = (const ull*)&swd[ci * 3 * 64];
#pragma unroll
            for (int cc = 0; cc < 4; cc++) {
                const ull w0 = wrow[0 * 64 + col + cc];
                const ull w1 = wrow[1 * 64 + col + cc];
                const ull w2 = wrow[2 * 64 + col + cc];
#pragma unroll
                for (int p = 0; p < 4; p++) {
                    // output pair (t, t+1): k=0 -> (x[t-1],x[t]) = xo[p]
                    //                       k=1 -> (x[t],x[t+1]) = xe[p]
                    //                       k=2 -> (x[t+1],x[t+2]) = xo[p+1]
                    acc[cc][p] = ffma2(w0, xo[p],     acc[cc][p]);
                    acc[cc][p] = ffma2(w1, xe[p],     acc[cc][p]);
                    acc[cc][p] = ffma2(w2, xo[p + 1], acc[cc][p]);
                }
            }
        }
        __syncthreads();
    }

    // ---- epilogue: bias (+ residual), float2 stores ----
#pragma unroll
    for (int cc = 0; cc < 4; cc++) {
        const int co = co0 + col + cc;
        const float bv = __ldg(&bias[co]);
        const size_t base = ((size_t)b * CO + co) * TLEN + t0 + tx * 8;
        float2* outp = (float2*)(y + base);
        if (res) {
            const float2* rp = (const float2*)(res + base);
#pragma unroll
            for (int p = 0; p < 4; p++) {
                float2 a = ull2f2(acc[cc][p]);
                float2 r = __ldg(&rp[p]);
                a.x += bv + r.x; a.y += bv + r.y;
                outp[p] = a;
            }
        } else {
#pragma unroll
            for (int p = 0; p < 4; p++) {
                float2 a = ull2f2(acc[cc][p]);
                a.x += bv; a.y += bv;
                outp[p] = a;
            }
        }
    }
}

// ---------------------------------------------------------------------------
// BN stage 1: one warp per (b, c) row -> partial sum / sumsq.
// ---------------------------------------------------------------------------
__global__ __launch_bounds__(256) void stats_kernel(
    const float* __restrict__ y, float* __restrict__ bs, float* __restrict__ bs2)
{
    const int warp = (int)((blockIdx.x * (size_t)blockDim.x + threadIdx.x) >> 5);
    const int lane = threadIdx.x & 31;
    if (warp >= BATCH * CO) return;
    const float4* p = (const float4*)(y + (size_t)warp * TLEN);
    float s = 0.f, s2 = 0.f;
#pragma unroll
    for (int i = lane; i < TLEN / 4; i += 32) {
        float4 v = p[i];
        s  += v.x + v.y + v.z + v.w;
        s2 += v.x * v.x + v.y * v.y + v.z * v.z + v.w * v.w;
    }
#pragma unroll
    for (int o = 16; o; o >>= 1) {
        s  += __shfl_xor_sync(0xFFFFFFFFu, s,  o);
        s2 += __shfl_xor_sync(0xFFFFFFFFu, s2, o);
    }
    if (lane == 0) { bs[warp] = s; bs2[warp] = s2; }
}

// ---------------------------------------------------------------------------
// BN stage 2: reduce per-(b,c) partials into per-(subject,c) scale/shift.
// ---------------------------------------------------------------------------
__global__ __launch_bounds__(256) void scaleshift_kernel(
    const float* __restrict__ bs, const float* __restrict__ bs2,
    const int* __restrict__ subj,
    const float* __restrict__ gamma, const float* __restrict__ beta,
    float* __restrict__ scale_out, float* __restrict__ shift_out)
{
    const int i = blockIdx.x * blockDim.x + threadIdx.x;   // s*CO + c
    if (i >= NSUBJ * CO) return;
    const int s = i / CO;
    const int c = i - s * CO;
    float sum = 0.f, sum2 = 0.f, cntb = 0.f;
    for (int b = 0; b < BATCH; b++) {
        if (subj[b] == s) {
            sum  += bs[b * CO + c];
            sum2 += bs2[b * CO + c];
            cntb += 1.f;
        }
    }
    const float cnt  = fmaxf(cntb * (float)TLEN, 1.f);
    const float mean = sum / cnt;
    const float var  = sum2 / cnt - mean * mean;
    const float sc   = gamma[i] * rsqrtf(var + BN_EPS);
    scale_out[i] = sc;
    shift_out[i] = beta[i] - mean * sc;
}

// ---------------------------------------------------------------------------
// BN stage 3: fused BN apply + exact-erf GELU, float4 vectorized.
// ---------------------------------------------------------------------------
__device__ __forceinline__ float gelu_exact(float u) {
    return 0.5f * u * (1.f + erff(u * 0.70710678118654752440f));
}

__global__ __launch_bounds__(256) void bn_gelu_kernel(
    const float* __restrict__ y, const int* __restrict__ subj,
    const float* __restrict__ scale, const float* __restrict__ shift,
    float* __restrict__ out)
{
    const size_t n4  = (size_t)BATCH * CO * TLEN / 4;
    const size_t idx = (size_t)blockIdx.x * blockDim.x + threadIdx.x;
    if (idx >= n4) return;
    const size_t e  = idx * 4;
    const int bc = (int)(e / TLEN);
    const int b  = bc / CO;
    const int c  = bc - b * CO;
    const int s  = __ldg(&subj[b]);
    const float sc = __ldg(&scale[s * CO + c]);
    const float sh = __ldg(&shift[s * CO + c]);
    float4 v = ((const float4*)y)[idx];
    v.x = gelu_exact(fmaf(v.x, sc, sh));
    v.y = gelu_exact(fmaf(v.y, sc, sh));
    v.z = gelu_exact(fmaf(v.z, sc, sh));
    v.w = gelu_exact(fmaf(v.w, sc, sh));
    ((float4*)out)[idx] = v;
}

// ---------------------------------------------------------------------------
// Host orchestration
// ---------------------------------------------------------------------------
static void run_bn_gelu(const float* y, const int* subj,
                        const float* gamma, const float* beta,
                        float* bsum, float* bsum2, float* scale, float* shift,
                        float* out)
{
    const int nrows = BATCH * CO;
    {
        const size_t threads = (size_t)nrows * 32;
        stats_kernel<<<(unsigned)((threads + 255) / 256), 256>>>(y, bsum, bsum2);
    }
    scaleshift_kernel<<<(NSUBJ * CO + 255) / 256, 256>>>(bsum, bsum2, subj,
                                                         gamma, beta, scale, shift);
    {
        const size_t n4 = (size_t)BATCH * CO * TLEN / 4;
        bn_gelu_kernel<<<(unsigned)((n4 + 255) / 256), 256>>>(y, subj, scale, shift, out);
    }
}

extern "C" void kernel_launch(void* const* d_in, const int* in_sizes, int n_in,
                              void* d_out, int out_size)
{
    const float* X    = (const float*)d_in[0];   // [256, 271, 512]
    const int*   subj = (const int*)  d_in[1];   // [256]
    const float* w0   = (const float*)d_in[2];
    const float* b0   = (const float*)d_in[3];
    const float* w1   = (const float*)d_in[4];
    const float* b1   = (const float*)d_in[5];
    const float* w2   = (const float*)d_in[6];
    const float* b2   = (const float*)d_in[7];
    const float* g0   = (const float*)d_in[8];
    const float* be0  = (const float*)d_in[9];
    const float* g1   = (const float*)d_in[10];
    const float* be1  = (const float*)d_in[11];
    const float* g2   = (const float*)d_in[12];
    const float* be2  = (const float*)d_in[13];
    float* out = (float*)d_out;

    const int Cin0    = in_sizes[0] / (BATCH * TLEN);   // 271
    const int Cin0Pad = (Cin0 + 7) & ~7;                // 272

    float *py, *pa, *pwt, *pbs, *pbs2, *psc, *psh;
    cudaGetSymbolAddress((void**)&py,   g_y);
    cudaGetSymbolAddress((void**)&pa,   g_a);
    cudaGetSymbolAddress((void**)&pwt,  g_wt);
    cudaGetSymbolAddress((void**)&pbs,  g_bsum);
    cudaGetSymbolAddress((void**)&pbs2, g_bsum2);
    cudaGetSymbolAddress((void**)&psc,  g_scale);
    cudaGetSymbolAddress((void**)&psh,  g_shift);

    float* wt0 = pwt;
    float* wt1 = pwt + WT_STRIDE;
    float* wt2 = pwt + 2 * WT_STRIDE;

    // transpose + zero-pad all weights up front
    {
        int n0 = Cin0Pad * 3 * CO;
        wtrans_kernel<<<(n0 + 255) / 256, 256>>>(w0, wt0, Cin0, Cin0Pad);
        int n1 = CO * 3 * CO;
        wtrans_kernel<<<(n1 + 255) / 256, 256>>>(w1, wt1, CO, CO);
        wtrans_kernel<<<(n1 + 255) / 256, 256>>>(w2, wt2, CO, CO);
    }

    dim3 cgrid(TLEN / 128, CO / 64, BATCH);   // (4, 5, 256)

    // layer 0: conv(X) -> y ; BN+GELU -> a
    conv3_f32x2_kernel<<<cgrid, 256>>>(X, wt0, b0, nullptr, py, Cin0);
    run_bn_gelu(py, subj, g0, be0, pbs, pbs2, psc, psh, pa);

    // layer 1: conv(a) + a -> y ; BN+GELU -> a
    conv3_f32x2_kernel<<<cgrid, 256>>>(pa, wt1, b1, pa, py, CO);
    run_bn_gelu(py, subj, g1, be1, pbs, pbs2, psc, psh, pa);

    // layer 2: conv(a) + a -> y ; BN+GELU -> out
    conv3_f32x2_kernel<<<cgrid, 256>>>(pa, wt2, b2, pa, py, CO);
    run_bn_gelu(py, subj, g2, be2, pbs, pbs2, psc, psh, out);
}

// round 6
// speedup vs baseline: 1.2373x; 1.0084x over previous
#include <cuda_runtime.h>
#include <math.h>
#include <stdint.h>

typedef unsigned long long ull;

#define BATCH 256
#define TLEN 512
#define CO 320
#define NSUBJ 4
#define BN_EPS 1e-5f
#define WTD_STRIDE (320 * 3 * 320)   // float2 elements per layer (max CinPad=320)

// ---------------------------------------------------------------------------
// Scratch (device globals; no allocation allowed)
// ---------------------------------------------------------------------------
__device__ float  g_y[(size_t)BATCH * CO * TLEN];   // conv output (pre-BN)
__device__ float  g_a[(size_t)BATCH * CO * TLEN];   // post BN+GELU activation
__device__ float2 g_wtd[3][WTD_STRIDE];             // transposed dup-pair weights
__device__ float  g_bsum[BATCH * CO];
__device__ float  g_bsum2[BATCH * CO];
__device__ float  g_scale[NSUBJ * CO];
__device__ float  g_shift[NSUBJ * CO];

// ---------------------------------------------------------------------------
// Packed fp32x2 helpers (Blackwell FFMA2; ptxas never emits from C++)
// ---------------------------------------------------------------------------
__device__ __forceinline__ ull ffma2(ull a, ull b, ull c) {
    ull d;
    asm("fma.rn.f32x2 %0, %1, %2, %3;" : "=l"(d) : "l"(a), "l"(b), "l"(c));
    return d;
}
__device__ __forceinline__ float2 u2f(ull v) {
    float2 r;
    asm("mov.b64 {%0, %1}, %2;" : "=f"(r.x), "=f"(r.y) : "l"(v));
    return r;
}
__device__ __forceinline__ ull packf2(float lo, float hi) {
    ull r;
    asm("mov.b64 %0, {%1, %2};" : "=l"(r) : "f"(lo), "f"(hi));
    return r;
}
__device__ __forceinline__ void cp_async8(uint32_t dst, const void* src, int src_bytes) {
    asm volatile("cp.async.ca.shared.global [%0], [%1], 8, %2;"
                 :: "r"(dst), "l"(src), "r"(src_bytes));
}
__device__ __forceinline__ void cp_async16(uint32_t dst, const void* src) {
    asm volatile("cp.async.cg.shared.global [%0], [%1], 16;"
                 :: "r"(dst), "l"(src));
}
__device__ __forceinline__ void cp_commit() {
    asm volatile("cp.async.commit_group;");
}
__device__ __forceinline__ void cp_wait1() {
    asm volatile("cp.async.wait_group 1;");
}
__device__ __forceinline__ void cp_wait0() {
    asm volatile("cp.async.wait_group 0;");
}
__device__ __forceinline__ uint32_t saddr(const void* p) {
    return (uint32_t)__cvta_generic_to_shared(p);
}

// ---------------------------------------------------------------------------
// Weight transpose: w[CO][Cin][3] -> wtd[(ci*3+k)][co] = (w, w) dup pairs,
// zero-padded to CinPad rows so staging is branch-free.
// ---------------------------------------------------------------------------
__global__ __launch_bounds__(256) void wtrans_kernel(
    const float* __restrict__ w, float2* __restrict__ wt, int Cin, int CinPad)
{
    const int i = blockIdx.x * blockDim.x + threadIdx.x;
    const int total = CinPad * 3 * CO;
    if (i >= total) return;
    const int co  = i % CO;
    const int row = i / CO;        // ci*3 + k
    const int ci  = row / 3;
    const int k   = row - ci * 3;
    const float v = (ci < Cin) ? w[((size_t)co * Cin + ci) * 3 + k] : 0.f;
    wt[i] = make_float2(v, v);
}

__global__ __launch_bounds__(256) void zero2_kernel(float* a, float* b)
{
    const int i = blockIdx.x * blockDim.x + threadIdx.x;
    if (i < BATCH * CO) { a[i] = 0.f; b[i] = 0.f; }
}

// ---------------------------------------------------------------------------
// Conv1d K=3 SAME, fp32x2 FMAs, cp.async double-buffered pipeline.
// Block tile: 64 co x 128 t, 256 threads; per thread 4 co x 4 t-pairs.
// x staged as even-start pairs only (odd-start pairs derived via mov.b64);
// weights staged as duplicated pairs copied raw from g_wtd.
// Fused: bias, residual, per-(b,co) BN partial stats (shuffle + atomicAdd).
// ---------------------------------------------------------------------------
// Shared x row layout: sxe[ci][phys(m)], m = 0..64 -> pair starting t0+2m,
//                      m = 65 -> left-boundary pair (t0-2, t0-1).
// phys(m) = m + 2*(m>>4)  (16B skew per 128B keeps LDS.128 conflict-free).
__global__ __launch_bounds__(256, 2) void conv3_pipe_kernel(
    const float*  __restrict__ x,     // [B, Cin, T]
    const float2* __restrict__ wtd,   // [CinPad*3, CO] dup pairs
    const float*  __restrict__ bias,  // [CO]
    const float*  __restrict__ res,   // [B, CO, T] or nullptr
    float* __restrict__ y,            // [B, CO, T]
    float* __restrict__ bsum, float* __restrict__ bsum2,
    int Cin)
{
    const int b   = blockIdx.z;
    const int co0 = blockIdx.y * 64;
    const int t0  = blockIdx.x * 128;
    const int tid = threadIdx.x;
    const int tx  = tid & 15;        // 4 t-pairs at pair index 4*tx
    const int ty  = tid >> 4;        // 4 co at co0 + ty*4

    __shared__ ull sxe[2][8][74];
    __shared__ ull swd[2][1536];     // [(ci*3+k)*64 + co] dup pairs

    const float*  xb = x + (size_t)b * Cin * TLEN;
    const float2* wb = wtd + (size_t)co0;   // + (c0*3 + r)*CO per row

    // precomputed skewed read indices
    const int m0  = 4 * tx;
    const int ph0 = m0 + 2 * (m0 >> 4);
    const int m4  = m0 + 4;
    const int ph4 = m4 + 2 * (m4 >> 4);
    const int mm  = (tx == 0) ? 65 : (m0 - 1);
    const int phm = mm + 2 * (mm >> 4);

    ull acc[4][4];
#pragma unroll
    for (int i = 0; i < 4; i++)
#pragma unroll
        for (int j = 0; j < 4; j++) acc[i][j] = 0ull;

    const int nch = (Cin + 7) >> 3;

    // ---- staging lambda-equivalent (inlined twice via macro) ----
#define STAGE_CHUNK(C0, BUF)                                                   \
    do {                                                                       \
        const int _c0 = (C0);                                                  \
        ull (*_sx)[74] = sxe[BUF];                                             \
        ull* _sw = swd[BUF];                                                   \
        for (int i = tid; i < 528; i += 256) {                                 \
            const int ci = i / 66;                                             \
            const int m  = i - ci * 66;                                        \
            const int g  = (m < 65) ? (t0 + 2 * m) : (t0 - 2);                 \
            const int c  = _c0 + ci;                                           \
            const bool ok = (g >= 0) & (g < 511) & (c < Cin);                  \
            const size_t off = ok ? ((size_t)c * TLEN + g) : 0;                \
            const int mp = m + 2 * (m >> 4);                                   \
            cp_async8(saddr(&_sx[ci][mp]), xb + off, ok ? 8 : 0);              \
        }                                                                      \
        const float2* _wr = wb + (size_t)(_c0 * 3) * CO;                       \
        for (int i = tid; i < 768; i += 256) {                                 \
            const int r  = i >> 5;                                             \
            const int cp = i & 31;                                             \
            cp_async16(saddr(&_sw[r * 64 + cp * 2]), _wr + (size_t)r * CO + cp * 2); \
        }                                                                      \
        cp_commit();                                                           \
    } while (0)

    STAGE_CHUNK(0, 0);

    for (int ch = 0; ch < nch; ch++) {
        const int buf = ch & 1;
        if (ch + 1 < nch) {
            STAGE_CHUNK((ch + 1) << 3, buf ^ 1);
            cp_wait1();
        } else {
            cp_wait0();
        }
        __syncthreads();

        const ull (*sx)[74] = sxe[buf];
        const ulonglong2* wp = (const ulonglong2*)swd[buf];

#pragma unroll
        for (int ci = 0; ci < 8; ci++) {
            const ull* rowx = sx[ci];
            ulonglong2 e01 = *(const ulonglong2*)(rowx + ph0);
            ulonglong2 e23 = *(const ulonglong2*)(rowx + ph0 + 2);
            const ull xe4u = rowx[ph4];
            const ull xmu  = rowx[phm];

            const float2 fm = u2f(xmu);
            const float2 f0 = u2f(e01.x), f1 = u2f(e01.y);
            const float2 f2 = u2f(e23.x), f3 = u2f(e23.y);
            const float2 f4 = u2f(xe4u);

            ull xe[4] = { e01.x, e01.y, e23.x, e23.y };
            ull xo[5] = { packf2(fm.y, f0.x), packf2(f0.y, f1.x),
                          packf2(f1.y, f2.x), packf2(f2.y, f3.x),
                          packf2(f3.y, f4.x) };

            const int wbase = ci * 96 + ty * 2;   // (ci*3+k)*32 + ty*2
            const ulonglong2 wk0a = wp[wbase],      wk0b = wp[wbase + 1];
            const ulonglong2 wk1a = wp[wbase + 32], wk1b = wp[wbase + 33];
            const ulonglong2 wk2a = wp[wbase + 64], wk2b = wp[wbase + 65];
            const ull w0[4] = { wk0a.x, wk0a.y, wk0b.x, wk0b.y };
            const ull w1[4] = { wk1a.x, wk1a.y, wk1b.x, wk1b.y };
            const ull w2[4] = { wk2a.x, wk2a.y, wk2b.x, wk2b.y };

#pragma unroll
            for (int cc = 0; cc < 4; cc++) {
#pragma unroll
                for (int p = 0; p < 4; p++) {
                    acc[cc][p] = ffma2(w0[cc], xo[p],     acc[cc][p]);
                    acc[cc][p] = ffma2(w1[cc], xe[p],     acc[cc][p]);
                    acc[cc][p] = ffma2(w2[cc], xo[p + 1], acc[cc][p]);
                }
            }
        }
        __syncthreads();
    }
#undef STAGE_CHUNK

    // ---- epilogue: bias (+ residual), stores, fused BN partial stats ----
    float ssum[4], ssq[4];
#pragma unroll
    for (int cc = 0; cc < 4; cc++) {
        const int co = co0 + ty * 4 + cc;
        const float bv = __ldg(&bias[co]);
        const size_t base = ((size_t)b * CO + co) * TLEN + t0 + tx * 8;
        float2* outp = (float2*)(y + base);
        const float2* rp = (const float2*)(res + base);   // unused if res==null
        float s = 0.f, q = 0.f;
#pragma unroll
        for (int p = 0; p < 4; p++) {
            float2 a = u2f(acc[cc][p]);
            a.x += bv; a.y += bv;
            if (res) {
                const float2 r = __ldg(&rp[p]);
                a.x += r.x; a.y += r.y;
            }
            outp[p] = a;
            s += a.x + a.y;
            q += a.x * a.x + a.y * a.y;
        }
        // reduce over the 16 tx lanes of this half-warp
#pragma unroll
        for (int off = 8; off; off >>= 1) {
            s += __shfl_down_sync(0xFFFFFFFFu, s, off, 16);
            q += __shfl_down_sync(0xFFFFFFFFu, q, off, 16);
        }
        ssum[cc] = s; ssq[cc] = q;
    }
    if ((tid & 15) == 0) {
#pragma unroll
        for (int cc = 0; cc < 4; cc++) {
            const int co = co0 + ty * 4 + cc;
            atomicAdd(&bsum [b * CO + co], ssum[cc]);
            atomicAdd(&bsum2[b * CO + co], ssq[cc]);
        }
    }
}

// ---------------------------------------------------------------------------
// BN stage 2: per-(subject,c) scale/shift from per-(b,c) partials.
// ---------------------------------------------------------------------------
__global__ __launch_bounds__(256) void scaleshift_kernel(
    const float* __restrict__ bs, const float* __restrict__ bs2,
    const int* __restrict__ subj,
    const float* __restrict__ gamma, const float* __restrict__ beta,
    float* __restrict__ scale_out, float* __restrict__ shift_out)
{
    const int i = blockIdx.x * blockDim.x + threadIdx.x;   // s*CO + c
    if (i >= NSUBJ * CO) return;
    const int s = i / CO;
    const int c = i - s * CO;
    float sum = 0.f, sum2 = 0.f, cntb = 0.f;
    for (int b = 0; b < BATCH; b++) {
        if (subj[b] == s) {
            sum  += bs[b * CO + c];
            sum2 += bs2[b * CO + c];
            cntb += 1.f;
        }
    }
    const float cnt  = fmaxf(cntb * (float)TLEN, 1.f);
    const float mean = sum / cnt;
    const float var  = sum2 / cnt - mean * mean;
    const float sc   = gamma[i] * rsqrtf(var + BN_EPS);
    scale_out[i] = sc;
    shift_out[i] = beta[i] - mean * sc;
}

// ---------------------------------------------------------------------------
// BN stage 3: fused BN apply + exact-erf GELU, float4 vectorized.
// ---------------------------------------------------------------------------
__device__ __forceinline__ float gelu_exact(float u) {
    return 0.5f * u * (1.f + erff(u * 0.70710678118654752440f));
}

__global__ __launch_bounds__(256) void bn_gelu_kernel(
    const float* __restrict__ y, const int* __restrict__ subj,
    const float* __restrict__ scale, const float* __restrict__ shift,
    float* __restrict__ out)
{
    const size_t n4  = (size_t)BATCH * CO * TLEN / 4;
    const size_t idx = (size_t)blockIdx.x * blockDim.x + threadIdx.x;
    if (idx >= n4) return;
    const size_t e  = idx * 4;
    const int bc = (int)(e / TLEN);
    const int b  = bc / CO;
    const int c  = bc - b * CO;
    const int s  = __ldg(&subj[b]);
    const float sc = __ldg(&scale[s * CO + c]);
    const float sh = __ldg(&shift[s * CO + c]);
    float4 v = ((const float4*)y)[idx];
    v.x = gelu_exact(fmaf(v.x, sc, sh));
    v.y = gelu_exact(fmaf(v.y, sc, sh));
    v.z = gelu_exact(fmaf(v.z, sc, sh));
    v.w = gelu_exact(fmaf(v.w, sc, sh));
    ((float4*)out)[idx] = v;
}

// ---------------------------------------------------------------------------
// Host orchestration
// ---------------------------------------------------------------------------
extern "C" void kernel_launch(void* const* d_in, const int* in_sizes, int n_in,
                              void* d_out, int out_size)
{
    const float* X    = (const float*)d_in[0];   // [256, 271, 512]
    const int*   subj = (const int*)  d_in[1];   // [256]
    const float* w0   = (const float*)d_in[2];
    const float* b0   = (const float*)d_in[3];
    const float* w1   = (const float*)d_in[4];
    const float* b1   = (const float*)d_in[5];
    const float* w2   = (const float*)d_in[6];
    const float* b2   = (const float*)d_in[7];
    const float* g0   = (const float*)d_in[8];
    const float* be0  = (const float*)d_in[9];
    const float* g1   = (const float*)d_in[10];
    const float* be1  = (const float*)d_in[11];
    const float* g2   = (const float*)d_in[12];
    const float* be2  = (const float*)d_in[13];
    float* out = (float*)d_out;

    const int Cin0    = in_sizes[0] / (BATCH * TLEN);   // 271
    const int Cin0Pad = (Cin0 + 7) & ~7;                // 272

    float *py, *pa, *pbs, *pbs2, *psc, *psh;
    float2* pwt;
    cudaGetSymbolAddress((void**)&py,   g_y);
    cudaGetSymbolAddress((void**)&pa,   g_a);
    cudaGetSymbolAddress((void**)&pwt,  g_wtd);
    cudaGetSymbolAddress((void**)&pbs,  g_bsum);
    cudaGetSymbolAddress((void**)&pbs2, g_bsum2);
    cudaGetSymbolAddress((void**)&psc,  g_scale);
    cudaGetSymbolAddress((void**)&psh,  g_shift);

    float2* wt0 = pwt;
    float2* wt1 = pwt + WTD_STRIDE;
    float2* wt2 = pwt + 2 * WTD_STRIDE;

    // transpose + dup + zero-pad all weights up front
    {
        const int n0 = Cin0Pad * 3 * CO;
        wtrans_kernel<<<(n0 + 255) / 256, 256>>>(w0, wt0, Cin0, Cin0Pad);
        const int n1 = CO * 3 * CO;
        wtrans_kernel<<<(n1 + 255) / 256, 256>>>(w1, wt1, CO, CO);
        wtrans_kernel<<<(n1 + 255) / 256, 256>>>(w2, wt2, CO, CO);
    }

    const dim3 cgrid(TLEN / 128, CO / 64, BATCH);   // (4, 5, 256)
    const int  zgrid = (BATCH * CO + 255) / 256;
    const unsigned bngrid = (unsigned)(((size_t)BATCH * CO * TLEN / 4 + 255) / 256);
    const int  ssgrid = (NSUBJ * CO + 255) / 256;

    // layer 0: conv(X) -> y (+stats) ; BN+GELU -> a
    zero2_kernel<<<zgrid, 256>>>(pbs, pbs2);
    conv3_pipe_kernel<<<cgrid, 256>>>(X, wt0, b0, nullptr, py, pbs, pbs2, Cin0);
    scaleshift_kernel<<<ssgrid, 256>>>(pbs, pbs2, subj, g0, be0, psc, psh);
    bn_gelu_kernel<<<bngrid, 256>>>(py, subj, psc, psh, pa);

    // layer 1: conv(a) + a -> y (+stats) ; BN+GELU -> a
    zero2_kernel<<<zgrid, 256>>>(pbs, pbs2);
    conv3_pipe_kernel<<<cgrid, 256>>>(pa, wt1, b1, pa, py, pbs, pbs2, CO);
    scaleshift_kernel<<<ssgrid, 256>>>(pbs, pbs2, subj, g1, be1, psc, psh);
    bn_gelu_kernel<<<bngrid, 256>>>(py, subj, psc, psh, pa);

    // layer 2: conv(a) + a -> y (+stats) ; BN+GELU -> out
    zero2_kernel<<<zgrid, 256>>>(pbs, pbs2);
    conv3_pipe_kernel<<<cgrid, 256>>>(pa, wt2, b2, pa, py, pbs, pbs2, CO);
    scaleshift_kernel<<<ssgrid, 256>>>(pbs, pbs2, subj, g2, be2, psc, psh);
    bn_gelu_kernel<<<bngrid, 256>>>(py, subj, psc, psh, out);
}

// round 8
// speedup vs baseline: 4.0235x; 3.2518x over previous
#include <cuda_runtime.h>
#include <cuda_bf16.h>
#include <math.h>
#include <stdint.h>

typedef unsigned long long ull;

#define BATCH 256
#define TLEN 512
#define CO 320
#define CIPAD 320
#define NSUBJ 4
#define BN_EPS 1e-5f
#define TROWS 514            // 1 zero halo row each side of 512
#define WBF_LAYER (3 * 2 * CO * CIPAD)   // [k][term][co][ci]

// ---------------------------------------------------------------------------
// Scratch (device globals; no allocation allowed)
// ---------------------------------------------------------------------------
__device__ float g_y[(size_t)BATCH * CO * TLEN];     // conv out (pre-BN)
__device__ float g_afp[(size_t)BATCH * CO * TLEN];   // fp32 activation (residual)
__device__ __align__(256) __nv_bfloat16 g_aT_hi[(size_t)BATCH * TROWS * CIPAD];
__device__ __align__(256) __nv_bfloat16 g_aT_lo[(size_t)BATCH * TROWS * CIPAD];
__device__ __align__(256) __nv_bfloat16 g_wbf[3][WBF_LAYER];
__device__ float g_bsum[BATCH * CO];
__device__ float g_bsum2[BATCH * CO];
__device__ float g_scale[NSUBJ * CO];
__device__ float g_shift[NSUBJ * CO];

// ---------------------------------------------------------------------------
// Helpers (all plain sm_103 features: cp.async, ldmatrix, mma.sync bf16)
// ---------------------------------------------------------------------------
__device__ __forceinline__ uint32_t smem_u32(const void* p) {
    return (uint32_t)__cvta_generic_to_shared(p);
}
__device__ __forceinline__ uint32_t swz128(uint32_t off) {
    return off ^ ((off >> 3) & 0x70);
}
__device__ __forceinline__ void cp16(uint32_t dst, const void* src) {
    asm volatile("cp.async.cg.shared.global [%0], [%1], 16;" :: "r"(dst), "l"(src));
}
__device__ __forceinline__ void cp_commit() { asm volatile("cp.async.commit_group;"); }
__device__ __forceinline__ void cp_wait0()  { asm volatile("cp.async.wait_group 0;"); }

__device__ __forceinline__ void ldsm_x4(uint32_t addr, uint32_t* r) {
    asm volatile("ldmatrix.sync.aligned.m8n8.x4.shared.b16 {%0,%1,%2,%3}, [%4];"
                 : "=r"(r[0]), "=r"(r[1]), "=r"(r[2]), "=r"(r[3]) : "r"(addr));
}
__device__ __forceinline__ void mma_bf16(float* c, const uint32_t* a,
                                         uint32_t b0, uint32_t b1) {
    asm volatile(
        "mma.sync.aligned.m16n8k16.row.col.f32.bf16.bf16.f32 "
        "{%0,%1,%2,%3}, {%4,%5,%6,%7}, {%8,%9}, {%0,%1,%2,%3};"
        : "+f"(c[0]), "+f"(c[1]), "+f"(c[2]), "+f"(c[3])
        : "r"(a[0]), "r"(a[1]), "r"(a[2]), "r"(a[3]), "r"(b0), "r"(b1));
}

// ---------------------------------------------------------------------------
// One-time transforms
// ---------------------------------------------------------------------------
// w[CO][Cin][3] -> wbf[k][term][co][ci(320 pad)] bf16 (term0=hi, term1=lo)
__global__ __launch_bounds__(256) void wtrans_kernel(
    const float* __restrict__ w, __nv_bfloat16* __restrict__ wbf, int Cin)
{
    const int i = blockIdx.x * blockDim.x + threadIdx.x;
    if (i >= WBF_LAYER) return;
    const int k    = i / (2 * CO * CIPAD);
    int r          = i - k * (2 * CO * CIPAD);
    const int term = r / (CO * CIPAD);
    r             -= term * (CO * CIPAD);
    const int co   = r / CIPAD;
    const int ci   = r - co * CIPAD;
    float val = (ci < Cin) ? w[((size_t)co * Cin + ci) * 3 + k] : 0.f;
    __nv_bfloat16 hi = __float2bfloat16(val);
    wbf[i] = (term == 0) ? hi : __float2bfloat16(val - __bfloat162float(hi));
}

// X[b][ci][t] fp32 -> aT_hi/lo[b][1+t][ci] bf16, zero halo rows, zero ci pad.
__global__ __launch_bounds__(256) void xt_kernel(
    const float* __restrict__ X,
    __nv_bfloat16* __restrict__ aT_hi, __nv_bfloat16* __restrict__ aT_lo,
    int Cin)
{
    __shared__ float tile[32][33];
    const int b     = blockIdx.z;
    const int ci0   = blockIdx.y * 32;
    const int trow0 = blockIdx.x * 32;
    const int tx = threadIdx.x, ty = threadIdx.y;

#pragma unroll
    for (int j = 0; j < 4; j++) {
        const int ci   = ci0 + ty + 8 * j;
        const int trow = trow0 + tx;
        const int tg   = trow - 1;
        float v = 0.f;
        if (ci < Cin && trow < TROWS && tg >= 0 && tg < TLEN)
            v = X[((size_t)b * Cin + ci) * TLEN + tg];
        tile[ty + 8 * j][tx] = v;
    }
    __syncthreads();
#pragma unroll
    for (int j = 0; j < 4; j++) {
        const int trow = trow0 + ty + 8 * j;
        const int ci   = ci0 + tx;
        if (trow < TROWS) {
            const float v = tile[tx][ty + 8 * j];
            const __nv_bfloat16 hi = __float2bfloat16(v);
            const size_t idx = ((size_t)b * TROWS + trow) * CIPAD + ci;
            aT_hi[idx] = hi;
            aT_lo[idx] = __float2bfloat16(v - __bfloat162float(hi));
        }
    }
}

// ---------------------------------------------------------------------------
// Conv via mma.sync bf16-split implicit GEMM.
// Grid (4 t-tiles, 5 co-tiles, 256 b), 256 threads (8 warps, 4m x 2n).
// CTA tile: 128 t x 64 co. K = 5 ci-chunks x (3 taps x 64 ci) x 3 products.
// A staged once per ci-chunk (130 rows incl. tap halo), taps read shifted.
// ---------------------------------------------------------------------------
#define SM_AH 0
#define SM_AL 17408
#define SM_B  34816          // 6 tiles (tap,term) x 8192B
#define CONV_SMEM 84992

__global__ __launch_bounds__(256, 2) void conv_mma_kernel(
    const __nv_bfloat16* __restrict__ aT_hi,
    const __nv_bfloat16* __restrict__ aT_lo,
    const __nv_bfloat16* __restrict__ wbf,   // [k][term][co][ci]
    const float* __restrict__ bias,
    const float* __restrict__ afp,           // fp32 residual [b][co][t]
    int use_res,
    float* __restrict__ y)
{
    extern __shared__ char dsm[];
    const uint32_t sbase_raw = smem_u32(dsm);
    const uint32_t base = (sbase_raw + 1023u) & ~1023u;
    char* gbase = dsm + (base - sbase_raw);

    const int tid  = threadIdx.x;
    const int lane = tid & 31;
    const int wid  = tid >> 5;
    const int wm   = wid >> 1;       // 0..3 -> m offset 32*wm
    const int wn   = wid & 1;        // 0..1 -> n offset 32*wn
    const int t0   = blockIdx.x * 128;
    const int co0  = blockIdx.y * 64;
    const int b    = blockIdx.z;

    float c[2][4][4];
#pragma unroll
    for (int mi = 0; mi < 2; mi++)
#pragma unroll
        for (int ni = 0; ni < 4; ni++)
#pragma unroll
            for (int r = 0; r < 4; r++) c[mi][ni][r] = 0.f;

    // ldmatrix lane mappings
    const int a_m     = lane & 15;          // row within m16
    const int a_kh    = lane >> 4;          // k half (0/1)
    const int b_n     = (lane & 7) + ((lane >> 4) << 3);  // n within n16
    const int b_kh    = (lane >> 3) & 1;    // k half

    for (int blk = 0; blk < 5; blk++) {
        // ---- stage A: 2 terms x 130 rows x 64 ci (128B rows, SW128) ----
        for (int i = tid; i < 2080; i += 256) {
            const int term = (i >= 1040);
            const int r    = i - term * 1040;
            const int row  = r >> 3;
            const int ch   = r & 7;
            const __nv_bfloat16* src =
                (term ? aT_lo : aT_hi) +
                ((size_t)(b * TROWS + t0 + row) * CIPAD + blk * 64 + ch * 8);
            cp16(base + (term ? SM_AL : SM_AH) + swz128(row * 128 + ch * 16), src);
        }
        // ---- stage B: 3 taps x 2 terms x 64 co x 64 ci ----
        for (int i = tid; i < 3072; i += 256) {
            const int tile = i >> 9;          // tap*2 + term
            const int r    = i & 511;
            const int row  = r >> 3;
            const int ch   = r & 7;
            const __nv_bfloat16* src =
                wbf + ((size_t)(tile * CO + co0 + row) * CIPAD + blk * 64 + ch * 8);
            cp16(base + SM_B + tile * 8192 + swz128(row * 128 + ch * 16), src);
        }
        cp_commit();
        cp_wait0();
        __syncthreads();

        for (int tap = 0; tap < 3; tap++) {
#pragma unroll
            for (int kb = 0; kb < 4; kb++) {
                uint32_t Ah[2][4], Al[2][4];
#pragma unroll
                for (int mi = 0; mi < 2; mi++) {
                    const int row = wm * 32 + mi * 16 + a_m + tap;
                    const uint32_t off =
                        swz128((uint32_t)(row * 128 + kb * 32 + a_kh * 16));
                    ldsm_x4(base + SM_AH + off, Ah[mi]);
                    ldsm_x4(base + SM_AL + off, Al[mi]);
                }
                uint32_t Bh[2][4], Bl[2][4];
#pragma unroll
                for (int p = 0; p < 2; p++) {
                    const int n = wn * 32 + p * 16 + b_n;
                    const uint32_t off =
                        swz128((uint32_t)(n * 128 + kb * 32 + b_kh * 16));
                    ldsm_x4(base + SM_B + (tap * 2 + 0) * 8192 + off, Bh[p]);
                    ldsm_x4(base + SM_B + (tap * 2 + 1) * 8192 + off, Bl[p]);
                }
#pragma unroll
                for (int mi = 0; mi < 2; mi++)
#pragma unroll
                    for (int ni = 0; ni < 4; ni++) {
                        const int p = ni >> 1, s = (ni & 1) * 2;
                        mma_bf16(c[mi][ni], Ah[mi], Bh[p][s], Bh[p][s + 1]);
                        mma_bf16(c[mi][ni], Al[mi], Bh[p][s], Bh[p][s + 1]);
                        mma_bf16(c[mi][ni], Ah[mi], Bl[p][s], Bl[p][s + 1]);
                    }
            }
        }
        __syncthreads();
    }

    // ---- epilogue: accumulators -> smem [co][t] -> coalesced global ----
    float* sD = (float*)gbase;   // [64][132]
#pragma unroll
    for (int mi = 0; mi < 2; mi++)
#pragma unroll
        for (int ni = 0; ni < 4; ni++)
#pragma unroll
            for (int r = 0; r < 4; r++) {
                const int m = wm * 32 + mi * 16 + (lane >> 2) + ((r >> 1) * 8);
                const int n = wn * 32 + ni * 8 + (lane & 3) * 2 + (r & 1);
                sD[n * 132 + m] = c[mi][ni][r];
            }
    __syncthreads();

    for (int i = tid; i < 2048; i += 256) {
        const int co = i >> 5;
        const int tq = i & 31;
        float4 v = *(const float4*)&sD[co * 132 + tq * 4];
        const float bv = __ldg(&bias[co0 + co]);
        const size_t gaddr = ((size_t)b * CO + co0 + co) * TLEN + t0 + tq * 4;
        v.x += bv; v.y += bv; v.z += bv; v.w += bv;
        if (use_res) {
            const float4 rr = __ldg((const float4*)&afp[gaddr]);
            v.x += rr.x; v.y += rr.y; v.z += rr.z; v.w += rr.w;
        }
        *(float4*)&y[gaddr] = v;
    }
}

// ---------------------------------------------------------------------------
// BN stage 1: one warp per (b, c) row -> sum / sumsq.
// ---------------------------------------------------------------------------
__global__ __launch_bounds__(256) void stats_kernel(
    const float* __restrict__ y, float* __restrict__ bs, float* __restrict__ bs2)
{
    const int warp = (int)((blockIdx.x * (size_t)blockDim.x + threadIdx.x) >> 5);
    const int lane = threadIdx.x & 31;
    if (warp >= BATCH * CO) return;
    const float4* p = (const float4*)(y + (size_t)warp * TLEN);
    float s = 0.f, s2 = 0.f;
#pragma unroll
    for (int i = lane; i < TLEN / 4; i += 32) {
        float4 v = p[i];
        s  += v.x + v.y + v.z + v.w;
        s2 += v.x * v.x + v.y * v.y + v.z * v.z + v.w * v.w;
    }
#pragma unroll
    for (int o = 16; o; o >>= 1) {
        s  += __shfl_xor_sync(0xFFFFFFFFu, s,  o);
        s2 += __shfl_xor_sync(0xFFFFFFFFu, s2, o);
    }
    if (lane == 0) { bs[warp] = s; bs2[warp] = s2; }
}

// ---------------------------------------------------------------------------
// BN stage 2: per-(subject,c) scale/shift.
// ---------------------------------------------------------------------------
__global__ __launch_bounds__(256) void scaleshift_kernel(
    const float* __restrict__ bs, const float* __restrict__ bs2,
    const int* __restrict__ subj,
    const float* __restrict__ gamma, const float* __restrict__ beta,
    float* __restrict__ scale_out, float* __restrict__ shift_out)
{
    const int i = blockIdx.x * blockDim.x + threadIdx.x;
    if (i >= NSUBJ * CO) return;
    const int s = i / CO;
    const int c = i - s * CO;
    float sum = 0.f, sum2 = 0.f, cntb = 0.f;
    for (int b = 0; b < BATCH; b++) {
        if (subj[b] == s) {
            sum  += bs[b * CO + c];
            sum2 += bs2[b * CO + c];
            cntb += 1.f;
        }
    }
    const float cnt  = fmaxf(cntb * (float)TLEN, 1.f);
    const float mean = sum / cnt;
    const float var  = sum2 / cnt - mean * mean;
    const float sc   = gamma[i] * rsqrtf(var + BN_EPS);
    scale_out[i] = sc;
    shift_out[i] = beta[i] - mean * sc;
}

__device__ __forceinline__ float gelu_exact(float u) {
    return 0.5f * u * (1.f + erff(u * 0.70710678118654752440f));
}

// ---------------------------------------------------------------------------
// BN+GELU: fp32 activation out (coalesced) + transposed bf16 hi/lo split.
// ---------------------------------------------------------------------------
__global__ __launch_bounds__(256) void bn_gelu_T_kernel(
    const float* __restrict__ y, const int* __restrict__ subj,
    const float* __restrict__ scale, const float* __restrict__ shift,
    float* __restrict__ afp,
    __nv_bfloat16* __restrict__ aT_hi, __nv_bfloat16* __restrict__ aT_lo)
{
    __shared__ float tile[32][33];
    const int b   = blockIdx.z;
    const int co0 = blockIdx.y * 32;
    const int t0  = blockIdx.x * 32;
    const int tx = threadIdx.x, ty = threadIdx.y;
    const int s = __ldg(&subj[b]);

#pragma unroll
    for (int j = 0; j < 4; j++) {
        const int co = co0 + ty + 8 * j;
        const float sc = __ldg(&scale[s * CO + co]);
        const float sh = __ldg(&shift[s * CO + co]);
        const size_t gaddr = ((size_t)b * CO + co) * TLEN + t0 + tx;
        const float act = gelu_exact(fmaf(y[gaddr], sc, sh));
        afp[gaddr] = act;
        tile[ty + 8 * j][tx] = act;
    }
    __syncthreads();
#pragma unroll
    for (int j = 0; j < 4; j++) {
        const int t  = t0 + ty + 8 * j;
        const int co = co0 + tx;
        const float v = tile[tx][ty + 8 * j];
        const __nv_bfloat16 hi = __float2bfloat16(v);
        const size_t idx = ((size_t)b * TROWS + 1 + t) * CIPAD + co;
        aT_hi[idx] = hi;
        aT_lo[idx] = __float2bfloat16(v - __bfloat162float(hi));
    }
}

// ---------------------------------------------------------------------------
// Final BN+GELU (fp32 out, no transpose).
// ---------------------------------------------------------------------------
__global__ __launch_bounds__(256) void bn_gelu_kernel(
    const float* __restrict__ y, const int* __restrict__ subj,
    const float* __restrict__ scale, const float* __restrict__ shift,
    float* __restrict__ out)
{
    const size_t n4  = (size_t)BATCH * CO * TLEN / 4;
    const size_t idx = (size_t)blockIdx.x * blockDim.x + threadIdx.x;
    if (idx >= n4) return;
    const size_t e  = idx * 4;
    const int bc = (int)(e / TLEN);
    const int b  = bc / CO;
    const int c  = bc - b * CO;
    const int s  = __ldg(&subj[b]);
    const float sc = __ldg(&scale[s * CO + c]);
    const float sh = __ldg(&shift[s * CO + c]);
    float4 v = ((const float4*)y)[idx];
    v.x = gelu_exact(fmaf(v.x, sc, sh));
    v.y = gelu_exact(fmaf(v.y, sc, sh));
    v.z = gelu_exact(fmaf(v.z, sc, sh));
    v.w = gelu_exact(fmaf(v.w, sc, sh));
    ((float4*)out)[idx] = v;
}

// ---------------------------------------------------------------------------
// Host orchestration
// ---------------------------------------------------------------------------
extern "C" void kernel_launch(void* const* d_in, const int* in_sizes, int n_in,
                              void* d_out, int out_size)
{
    const float* X    = (const float*)d_in[0];
    const int*   subj = (const int*)  d_in[1];
    const float* w0   = (const float*)d_in[2];
    const float* b0   = (const float*)d_in[3];
    const float* w1   = (const float*)d_in[4];
    const float* b1   = (const float*)d_in[5];
    const float* w2   = (const float*)d_in[6];
    const float* b2   = (const float*)d_in[7];
    const float* g0   = (const float*)d_in[8];
    const float* be0  = (const float*)d_in[9];
    const float* g1   = (const float*)d_in[10];
    const float* be1  = (const float*)d_in[11];
    const float* g2   = (const float*)d_in[12];
    const float* be2  = (const float*)d_in[13];
    float* out = (float*)d_out;

    const int Cin0 = in_sizes[0] / (BATCH * TLEN);   // 271

    float *py, *pafp, *pbs, *pbs2, *psc, *psh;
    __nv_bfloat16 *pah, *pal, *pwb;
    cudaGetSymbolAddress((void**)&py,   g_y);
    cudaGetSymbolAddress((void**)&pafp, g_afp);
    cudaGetSymbolAddress((void**)&pah,  g_aT_hi);
    cudaGetSymbolAddress((void**)&pal,  g_aT_lo);
    cudaGetSymbolAddress((void**)&pwb,  g_wbf);
    cudaGetSymbolAddress((void**)&pbs,  g_bsum);
    cudaGetSymbolAddress((void**)&pbs2, g_bsum2);
    cudaGetSymbolAddress((void**)&psc,  g_scale);
    cudaGetSymbolAddress((void**)&psh,  g_shift);

    cudaFuncSetAttribute(conv_mma_kernel,
                         cudaFuncAttributeMaxDynamicSharedMemorySize, CONV_SMEM);

    // one-time transforms
    const int wgrid = (WBF_LAYER + 255) / 256;
    wtrans_kernel<<<wgrid, 256>>>(w0, pwb,                 Cin0);
    wtrans_kernel<<<wgrid, 256>>>(w1, pwb + WBF_LAYER,     CO);
    wtrans_kernel<<<wgrid, 256>>>(w2, pwb + 2 * WBF_LAYER, CO);
    xt_kernel<<<dim3(17, 10, BATCH), dim3(32, 8)>>>(X, pah, pal, Cin0);

    const dim3 cgrid(4, 5, BATCH);
    const unsigned sgrid  = (unsigned)(((size_t)BATCH * CO * 32 + 255) / 256);
    const int      ssgrid = (NSUBJ * CO + 255) / 256;
    const dim3 tgrid(16, 10, BATCH);
    const unsigned fgrid = (unsigned)(((size_t)BATCH * CO * TLEN / 4 + 255) / 256);

    // layer 0
    conv_mma_kernel<<<cgrid, 256, CONV_SMEM>>>(pah, pal, pwb, b0, pafp, 0, py);
    stats_kernel<<<sgrid, 256>>>(py, pbs, pbs2);
    scaleshift_kernel<<<ssgrid, 256>>>(pbs, pbs2, subj, g0, be0, psc, psh);
    bn_gelu_T_kernel<<<tgrid, dim3(32, 8)>>>(py, subj, psc, psh, pafp, pah, pal);

    // layer 1 (residual)
    conv_mma_kernel<<<cgrid, 256, CONV_SMEM>>>(pah, pal, pwb + WBF_LAYER, b1, pafp, 1, py);
    stats_kernel<<<sgrid, 256>>>(py, pbs, pbs2);
    scaleshift_kernel<<<ssgrid, 256>>>(pbs, pbs2, subj, g1, be1, psc, psh);
    bn_gelu_T_kernel<<<tgrid, dim3(32, 8)>>>(py, subj, psc, psh, pafp, pah, pal);

    // layer 2 (residual, final fp32 output)
    conv_mma_kernel<<<cgrid, 256, CONV_SMEM>>>(pah, pal, pwb + 2 * WBF_LAYER, b2, pafp, 1, py);
    stats_kernel<<<sgrid, 256>>>(py, pbs, pbs2);
    scaleshift_kernel<<<ssgrid, 256>>>(pbs, pbs2, subj, g2, be2, psc, psh);
    bn_gelu_kernel<<<fgrid, 256>>>(py, subj, psc, psh, out);
}

// round 11
// speedup vs baseline: 4.9510x; 1.2305x over previous
#include <cuda_runtime.h>
#include <cuda_fp16.h>
#include <math.h>
#include <stdint.h>

typedef unsigned long long ull;

#define BATCH 256
#define TLEN 512
#define CO 320
#define CIPAD 320
#define NSUBJ 4
#define BN_EPS 1e-5f
#define TROWS 514            // 1 zero halo row each side of 512
#define WH_LAYER (3 * CO * CIPAD)   // [k][co][ci] fp16

// ---------------------------------------------------------------------------
// Scratch (device globals; no allocation allowed)
// ---------------------------------------------------------------------------
__device__ float g_y[(size_t)BATCH * CO * TLEN];     // conv out (pre-BN)
__device__ float g_afp[(size_t)BATCH * CO * TLEN];   // fp32 activation (residual)
__device__ __align__(256) __half g_aT_hi[(size_t)BATCH * TROWS * CIPAD];
__device__ __align__(256) __half g_aT_lo[(size_t)BATCH * TROWS * CIPAD];
__device__ __align__(256) __half g_wh[3][WH_LAYER];
__device__ float g_bsum[BATCH * CO];
__device__ float g_bsum2[BATCH * CO];
__device__ float g_scale[NSUBJ * CO];
__device__ float g_shift[NSUBJ * CO];

// ---------------------------------------------------------------------------
// Helpers (plain sm_103: cp.async, ldmatrix, mma.sync fp16)
// ---------------------------------------------------------------------------
__device__ __forceinline__ uint32_t smem_u32(const void* p) {
    return (uint32_t)__cvta_generic_to_shared(p);
}
__device__ __forceinline__ uint32_t swz128(uint32_t off) {
    return off ^ ((off >> 3) & 0x70);
}
__device__ __forceinline__ void cp16(uint32_t dst, const void* src) {
    asm volatile("cp.async.cg.shared.global [%0], [%1], 16;" :: "r"(dst), "l"(src));
}
__device__ __forceinline__ void cp_commit() { asm volatile("cp.async.commit_group;"); }
__device__ __forceinline__ void cp_wait0()  { asm volatile("cp.async.wait_group 0;"); }

__device__ __forceinline__ void ldsm_x4(uint32_t addr, uint32_t* r) {
    asm volatile("ldmatrix.sync.aligned.m8n8.x4.shared.b16 {%0,%1,%2,%3}, [%4];"
                 : "=r"(r[0]), "=r"(r[1]), "=r"(r[2]), "=r"(r[3]) : "r"(addr));
}
__device__ __forceinline__ void mma_f16(float* c, const uint32_t* a,
                                        uint32_t b0, uint32_t b1) {
    asm volatile(
        "mma.sync.aligned.m16n8k16.row.col.f32.f16.f16.f32 "
        "{%0,%1,%2,%3}, {%4,%5,%6,%7}, {%8,%9}, {%0,%1,%2,%3};"
        : "+f"(c[0]), "+f"(c[1]), "+f"(c[2]), "+f"(c[3])
        : "r"(a[0]), "r"(a[1]), "r"(a[2]), "r"(a[3]), "r"(b0), "r"(b1));
}

// ---------------------------------------------------------------------------
// One-time transforms
// ---------------------------------------------------------------------------
// w[CO][Cin][3] -> wh[k][co][ci(320 pad)] fp16
__global__ __launch_bounds__(256) void wtrans_kernel(
    const float* __restrict__ w, __half* __restrict__ wh, int Cin)
{
    const int i = blockIdx.x * blockDim.x + threadIdx.x;
    if (i >= WH_LAYER) return;
    const int k  = i / (CO * CIPAD);
    int r        = i - k * (CO * CIPAD);
    const int co = r / CIPAD;
    const int ci = r - co * CIPAD;
    const float val = (ci < Cin) ? w[((size_t)co * Cin + ci) * 3 + k] : 0.f;
    wh[i] = __float2half_rn(val);
}

// X[b][ci][t] fp32 -> aT_hi/lo[b][1+t][ci] fp16 split, zero halo & ci pad.
__global__ __launch_bounds__(256) void xt_kernel(
    const float* __restrict__ X,
    __half* __restrict__ aT_hi, __half* __restrict__ aT_lo,
    int Cin)
{
    __shared__ float tile[32][33];
    const int b     = blockIdx.z;
    const int ci0   = blockIdx.y * 32;
    const int trow0 = blockIdx.x * 32;
    const int tx = threadIdx.x, ty = threadIdx.y;

#pragma unroll
    for (int j = 0; j < 4; j++) {
        const int ci   = ci0 + ty + 8 * j;
        const int trow = trow0 + tx;
        const int tg   = trow - 1;
        float v = 0.f;
        if (ci < Cin && trow < TROWS && tg >= 0 && tg < TLEN)
            v = X[((size_t)b * Cin + ci) * TLEN + tg];
        tile[ty + 8 * j][tx] = v;
    }
    __syncthreads();
#pragma unroll
    for (int j = 0; j < 4; j++) {
        const int trow = trow0 + ty + 8 * j;
        const int ci   = ci0 + tx;
        if (trow < TROWS) {
            const float v = tile[tx][ty + 8 * j];
            const __half hi = __float2half_rn(v);
            const size_t idx = ((size_t)b * TROWS + trow) * CIPAD + ci;
            aT_hi[idx] = hi;
            aT_lo[idx] = __float2half_rn(v - __half2float(hi));
        }
    }
}

// ---------------------------------------------------------------------------
// Conv via mma.sync fp16 2-product implicit GEMM.
// Grid (4 t, 5 co, 256 b), 256 threads (8 warps, 4m x 2n).
// CTA tile: 128 t x 64 co. K = 5 ci-chunks x 3 taps x 64 ci x 2 products.
// A staged once per ci-chunk (130 rows incl. tap halo), taps read shifted.
// ---------------------------------------------------------------------------
#define SM_AH 0
#define SM_AL 17408
#define SM_B  34816          // 3 tap tiles x 8192B
#define CONV_SMEM 60416

__global__ __launch_bounds__(256, 2) void conv_mma_kernel(
    const __half* __restrict__ aT_hi,
    const __half* __restrict__ aT_lo,
    const __half* __restrict__ wh,     // [k][co][ci]
    const float* __restrict__ bias,
    const float* __restrict__ afp,     // fp32 residual [b][co][t]
    int use_res,
    float* __restrict__ y)
{
    extern __shared__ char dsm[];
    const uint32_t sbase_raw = smem_u32(dsm);
    const uint32_t base = (sbase_raw + 1023u) & ~1023u;
    char* gbase = dsm + (base - sbase_raw);

    const int tid  = threadIdx.x;
    const int lane = tid & 31;
    const int wid  = tid >> 5;
    const int wm   = wid >> 1;       // 0..3 -> m offset 32*wm
    const int wn   = wid & 1;        // 0..1 -> n offset 32*wn
    const int t0   = blockIdx.x * 128;
    const int co0  = blockIdx.y * 64;
    const int b    = blockIdx.z;

    float c[2][4][4];
#pragma unroll
    for (int mi = 0; mi < 2; mi++)
#pragma unroll
        for (int ni = 0; ni < 4; ni++)
#pragma unroll
            for (int r = 0; r < 4; r++) c[mi][ni][r] = 0.f;

    const int a_m  = lane & 15;
    const int a_kh = lane >> 4;
    const int b_n  = (lane & 7) + ((lane >> 4) << 3);
    const int b_kh = (lane >> 3) & 1;

    for (int blk = 0; blk < 5; blk++) {
        // ---- stage A: 2 terms x 130 rows x 64 ci (128B rows, SW128) ----
        for (int i = tid; i < 2080; i += 256) {
            const int term = (i >= 1040);
            const int r    = i - term * 1040;
            const int row  = r >> 3;
            const int ch   = r & 7;
            const __half* src =
                (term ? aT_lo : aT_hi) +
                ((size_t)(b * TROWS + t0 + row) * CIPAD + blk * 64 + ch * 8);
            cp16(base + (term ? SM_AL : SM_AH) + swz128(row * 128 + ch * 16), src);
        }
        // ---- stage B: 3 taps x 64 co x 64 ci ----
        for (int i = tid; i < 1536; i += 256) {
            const int tap = i >> 9;
            const int r   = i & 511;
            const int row = r >> 3;
            const int ch  = r & 7;
            const __half* src =
                wh + ((size_t)(tap * CO + co0 + row) * CIPAD + blk * 64 + ch * 8);
            cp16(base + SM_B + tap * 8192 + swz128(row * 128 + ch * 16), src);
        }
        cp_commit();
        cp_wait0();
        __syncthreads();

        for (int tap = 0; tap < 3; tap++) {
#pragma unroll
            for (int kb = 0; kb < 4; kb++) {
                uint32_t Ah[2][4], Al[2][4];
#pragma unroll
                for (int mi = 0; mi < 2; mi++) {
                    const int row = wm * 32 + mi * 16 + a_m + tap;
                    const uint32_t off =
                        swz128((uint32_t)(row * 128 + kb * 32 + a_kh * 16));
                    ldsm_x4(base + SM_AH + off, Ah[mi]);
                    ldsm_x4(base + SM_AL + off, Al[mi]);
                }
                uint32_t Bh[2][4];
#pragma unroll
                for (int p = 0; p < 2; p++) {
                    const int n = wn * 32 + p * 16 + b_n;
                    const uint32_t off =
                        swz128((uint32_t)(n * 128 + kb * 32 + b_kh * 16));
                    ldsm_x4(base + SM_B + tap * 8192 + off, Bh[p]);
                }
#pragma unroll
                for (int mi = 0; mi < 2; mi++)
#pragma unroll
                    for (int ni = 0; ni < 4; ni++) {
                        const int p = ni >> 1, s = (ni & 1) * 2;
                        mma_f16(c[mi][ni], Ah[mi], Bh[p][s], Bh[p][s + 1]);
                        mma_f16(c[mi][ni], Al[mi], Bh[p][s], Bh[p][s + 1]);
                    }
            }
        }
        __syncthreads();
    }

    // ---- epilogue: accumulators -> smem [co][t] -> coalesced global ----
    float* sD = (float*)gbase;   // [64][132]
#pragma unroll
    for (int mi = 0; mi < 2; mi++)
#pragma unroll
        for (int ni = 0; ni < 4; ni++)
#pragma unroll
            for (int r = 0; r < 4; r++) {
                const int m = wm * 32 + mi * 16 + (lane >> 2) + ((r >> 1) * 8);
                const int n = wn * 32 + ni * 8 + (lane & 3) * 2 + (r & 1);
                sD[n * 132 + m] = c[mi][ni][r];
            }
    __syncthreads();

    for (int i = tid; i < 2048; i += 256) {
        const int co = i >> 5;
        const int tq = i & 31;
        float4 v = *(const float4*)&sD[co * 132 + tq * 4];
        const float bv = __ldg(&bias[co0 + co]);
        const size_t gaddr = ((size_t)b * CO + co0 + co) * TLEN + t0 + tq * 4;
        v.x += bv; v.y += bv; v.z += bv; v.w += bv;
        if (use_res) {
            const float4 rr = __ldg((const float4*)&afp[gaddr]);
            v.x += rr.x; v.y += rr.y; v.z += rr.z; v.w += rr.w;
        }
        *(float4*)&y[gaddr] = v;
    }
}

// ---------------------------------------------------------------------------
// BN stage 1: one warp per (b, c) row -> sum / sumsq (deterministic).
// ---------------------------------------------------------------------------
__global__ __launch_bounds__(256) void stats_kernel(
    const float* __restrict__ y, float* __restrict__ bs, float* __restrict__ bs2)
{
    const int warp = (int)((blockIdx.x * (size_t)blockDim.x + threadIdx.x) >> 5);
    const int lane = threadIdx.x & 31;
    if (warp >= BATCH * CO) return;
    const float4* p = (const float4*)(y + (size_t)warp * TLEN);
    float s = 0.f, s2 = 0.f;
#pragma unroll
    for (int i = lane; i < TLEN / 4; i += 32) {
        float4 v = p[i];
        s  += v.x + v.y + v.z + v.w;
        s2 += v.x * v.x + v.y * v.y + v.z * v.z + v.w * v.w;
    }
#pragma unroll
    for (int o = 16; o; o >>= 1) {
        s  += __shfl_xor_sync(0xFFFFFFFFu, s,  o);
        s2 += __shfl_xor_sync(0xFFFFFFFFu, s2, o);
    }
    if (lane == 0) { bs[warp] = s; bs2[warp] = s2; }
}

// ---------------------------------------------------------------------------
// BN stage 2: per-(subject,c) scale/shift.
// ---------------------------------------------------------------------------
__global__ __launch_bounds__(256) void scaleshift_kernel(
    const float* __restrict__ bs, const float* __restrict__ bs2,
    const int* __restrict__ subj,
    const float* __restrict__ gamma, const float* __restrict__ beta,
    float* __restrict__ scale_out, float* __restrict__ shift_out)
{
    const int i = blockIdx.x * blockDim.x + threadIdx.x;
    if (i >= NSUBJ * CO) return;
    const int s = i / CO;
    const int c = i - s * CO;
    float sum = 0.f, sum2 = 0.f, cntb = 0.f;
    for (int b = 0; b < BATCH; b++) {
        if (subj[b] == s) {
            sum  += bs[b * CO + c];
            sum2 += bs2[b * CO + c];
            cntb += 1.f;
        }
    }
    const float cnt  = fmaxf(cntb * (float)TLEN, 1.f);
    const float mean = sum / cnt;
    const float var  = sum2 / cnt - mean * mean;
    const float sc   = gamma[i] * rsqrtf(var + BN_EPS);
    scale_out[i] = sc;
    shift_out[i] = beta[i] - mean * sc;
}

__device__ __forceinline__ float gelu_exact(float u) {
    return 0.5f * u * (1.f + erff(u * 0.70710678118654752440f));
}

// ---------------------------------------------------------------------------
// BN+GELU: fp32 activation out (coalesced) + transposed fp16 hi/lo split.
// ---------------------------------------------------------------------------
__global__ __launch_bounds__(256) void bn_gelu_T_kernel(
    const float* __restrict__ y, const int* __restrict__ subj,
    const float* __restrict__ scale, const float* __restrict__ shift,
    float* __restrict__ afp,
    __half* __restrict__ aT_hi, __half* __restrict__ aT_lo)
{
    __shared__ float tile[32][33];
    const int b   = blockIdx.z;
    const int co0 = blockIdx.y * 32;
    const int t0  = blockIdx.x * 32;
    const int tx = threadIdx.x, ty = threadIdx.y;
    const int s = __ldg(&subj[b]);

#pragma unroll
    for (int j = 0; j < 4; j++) {
        const int co = co0 + ty + 8 * j;
        const float sc = __ldg(&scale[s * CO + co]);
        const float sh = __ldg(&shift[s * CO + co]);
        const size_t gaddr = ((size_t)b * CO + co) * TLEN + t0 + tx;
        const float act = gelu_exact(fmaf(y[gaddr], sc, sh));
        afp[gaddr] = act;
        tile[ty + 8 * j][tx] = act;
    }
    __syncthreads();
#pragma unroll
    for (int j = 0; j < 4; j++) {
        const int t  = t0 + ty + 8 * j;
        const int co = co0 + tx;
        const float v = tile[tx][ty + 8 * j];
        const __half hi = __float2half_rn(v);
        const size_t idx = ((size_t)b * TROWS + 1 + t) * CIPAD + co;
        aT_hi[idx] = hi;
        aT_lo[idx] = __float2half_rn(v - __half2float(hi));
    }
}

// ---------------------------------------------------------------------------
// Final BN+GELU (fp32 out, no transpose).
// ---------------------------------------------------------------------------
__global__ __launch_bounds__(256) void bn_gelu_kernel(
    const float* __restrict__ y, const int* __restrict__ subj,
    const float* __restrict__ scale, const float* __restrict__ shift,
    float* __restrict__ out)
{
    const size_t n4  = (size_t)BATCH * CO * TLEN / 4;
    const size_t idx = (size_t)blockIdx.x * blockDim.x + threadIdx.x;
    if (idx >= n4) return;
    const size_t e  = idx * 4;
    const int bc = (int)(e / TLEN);
    const int b  = bc / CO;
    const int c  = bc - b * CO;
    const int s  = __ldg(&subj[b]);
    const float sc = __ldg(&scale[s * CO + c]);
    const float sh = __ldg(&shift[s * CO + c]);
    float4 v = ((const float4*)y)[idx];
    v.x = gelu_exact(fmaf(v.x, sc, sh));
    v.y = gelu_exact(fmaf(v.y, sc, sh));
    v.z = gelu_exact(fmaf(v.z, sc, sh));
    v.w = gelu_exact(fmaf(v.w, sc, sh));
    ((float4*)out)[idx] = v;
}

// ---------------------------------------------------------------------------
// Host orchestration
// ---------------------------------------------------------------------------
extern "C" void kernel_launch(void* const* d_in, const int* in_sizes, int n_in,
                              void* d_out, int out_size)
{
    const float* X    = (const float*)d_in[0];
    const int*   subj = (const int*)  d_in[1];
    const float* w0   = (const float*)d_in[2];
    const float* b0   = (const float*)d_in[3];
    const float* w1   = (const float*)d_in[4];
    const float* b1   = (const float*)d_in[5];
    const float* w2   = (const float*)d_in[6];
    const float* b2   = (const float*)d_in[7];
    const float* g0   = (const float*)d_in[8];
    const float* be0  = (const float*)d_in[9];
    const float* g1   = (const float*)d_in[10];
    const float* be1  = (const float*)d_in[11];
    const float* g2   = (const float*)d_in[12];
    const float* be2  = (const float*)d_in[13];
    float* out = (float*)d_out;

    const int Cin0 = in_sizes[0] / (BATCH * TLEN);   // 271

    float *py, *pafp, *pbs, *pbs2, *psc, *psh;
    __half *pah, *pal, *pwh;
    cudaGetSymbolAddress((void**)&py,   g_y);
    cudaGetSymbolAddress((void**)&pafp, g_afp);
    cudaGetSymbolAddress((void**)&pah,  g_aT_hi);
    cudaGetSymbolAddress((void**)&pal,  g_aT_lo);
    cudaGetSymbolAddress((void**)&pwh,  g_wh);
    cudaGetSymbolAddress((void**)&pbs,  g_bsum);
    cudaGetSymbolAddress((void**)&pbs2, g_bsum2);
    cudaGetSymbolAddress((void**)&psc,  g_scale);
    cudaGetSymbolAddress((void**)&psh,  g_shift);

    cudaFuncSetAttribute(conv_mma_kernel,
                         cudaFuncAttributeMaxDynamicSharedMemorySize, CONV_SMEM);

    // one-time transforms
    const int wgrid = (WH_LAYER + 255) / 256;
    wtrans_kernel<<<wgrid, 256>>>(w0, pwh,                Cin0);
    wtrans_kernel<<<wgrid, 256>>>(w1, pwh + WH_LAYER,     CO);
    wtrans_kernel<<<wgrid, 256>>>(w2, pwh + 2 * WH_LAYER, CO);
    xt_kernel<<<dim3(17, 10, BATCH), dim3(32, 8)>>>(X, pah, pal, Cin0);

    const dim3 cgrid(4, 5, BATCH);
    const unsigned sgrid  = (unsigned)(((size_t)BATCH * CO * 32 + 255) / 256);
    const int      ssgrid = (NSUBJ * CO + 255) / 256;
    const dim3 tgrid(16, 10, BATCH);
    const unsigned fgrid = (unsigned)(((size_t)BATCH * CO * TLEN / 4 + 255) / 256);

    // layer 0
    conv_mma_kernel<<<cgrid, 256, CONV_SMEM>>>(pah, pal, pwh, b0, pafp, 0, py);
    stats_kernel<<<sgrid, 256>>>(py, pbs, pbs2);
    scaleshift_kernel<<<ssgrid, 256>>>(pbs, pbs2, subj, g0, be0, psc, psh);
    bn_gelu_T_kernel<<<tgrid, dim3(32, 8)>>>(py, subj, psc, psh, pafp, pah, pal);

    // layer 1 (residual)
    conv_mma_kernel<<<cgrid, 256, CONV_SMEM>>>(pah, pal, pwh + WH_LAYER, b1, pafp, 1, py);
    stats_kernel<<<sgrid, 256>>>(py, pbs, pbs2);
    scaleshift_kernel<<<ssgrid, 256>>>(pbs, pbs2, subj, g1, be1, psc, psh);
    bn_gelu_T_kernel<<<tgrid, dim3(32, 8)>>>(py, subj, psc, psh, pafp, pah, pal);

    // layer 2 (residual, final fp32 output)
    conv_mma_kernel<<<cgrid, 256, CONV_SMEM>>>(pah, pal, pwh + 2 * WH_LAYER, b2, pafp, 1, py);
    stats_kernel<<<sgrid, 256>>>(py, pbs, pbs2);
    scaleshift_kernel<<<ssgrid, 256>>>(pbs, pbs2, subj, g2, be2, psc, psh);
    bn_gelu_kernel<<<fgrid, 256>>>(py, subj, psc, psh, out);
}